// round 8
// baseline (speedup 1.0000x reference)
#include <cuda_runtime.h>
#include <cstdint>
#include <math.h>

// Problem constants
#define BATCH_ 4096
#define HID_   2048
#define KDIM_  2048

// GEMM tile config
#define BM 128
#define BN 128
#define BK 16
#define LDA_S (BM + 4)   // padded shared A leading dim (132 floats; 16B-aligned rows)

// Scratch for the 4 gate pre-activations: 4 * 4096 * 2048 f32 = 134 MB.
// __device__ global (allocation-free per harness rules).
__device__ float g_gates[(size_t)4 * BATCH_ * HID_];

__device__ __forceinline__ unsigned long long pack2_dup(float a) {
    unsigned long long r;
    asm("mov.b64 %0, {%1, %1};" : "=l"(r) : "f"(a));
    return r;
}

__device__ __forceinline__ unsigned long long ffma2(unsigned long long a,
                                                    unsigned long long b,
                                                    unsigned long long c) {
    unsigned long long d;
    asm("fma.rn.f32x2 %0, %1, %2, %3;" : "=l"(d) : "l"(a), "l"(b), "l"(c));
    return d;
}

// gates[g][b][n] = sum_k x[b][k] * w_ih[g][k][n] + sum_k h[b][k] * w_hh[g][k][n]
// (biases added in the epilogue)
//
// Unified K loop of length 2*KDIM_: first half reads (x, w_ih), second half (h, w_hh),
// accumulating into the same register tile.
__global__ __launch_bounds__(256, 2) void gates_gemm_kernel(
    const float* __restrict__ x, const float* __restrict__ h,
    const float* __restrict__ w_ih, const float* __restrict__ w_hh)
{
    const int gate = blockIdx.z;
    const int m0 = blockIdx.x * BM;   // batch tile (x-fastest => weight-panel L2 reuse)
    const int n0 = blockIdx.y * BN;   // hidden tile

    const float* __restrict__ Wih = w_ih + (size_t)gate * KDIM_ * HID_;
    const float* __restrict__ Whh = w_hh + (size_t)gate * KDIM_ * HID_;

    __shared__ float As[BK * LDA_S];  // transposed: As[k][m]
    __shared__ float Bs[BK * BN];     // Bs[k][n]

    const int tid = threadIdx.x;
    const int tx = tid & 15;          // 16 col groups
    const int ty = tid >> 4;          // 16 row groups

    // A-tile (128 rows x 16 k) as 512 float4: 2 per thread (rows aRow, aRow+64)
    const int aRow = tid >> 2;            // 0..63
    const int aK   = (tid & 3) * 4;       // 0,4,8,12
    // B-tile (16 k x 128 n) as 512 float4: 2 per thread (k rows bRow, bRow+8)
    const int bRow = tid >> 5;            // 0..7
    const int bCol = (tid & 31) * 4;      // 0..124

    unsigned long long acc[8][4];
    #pragma unroll
    for (int i = 0; i < 8; i++) {
        #pragma unroll
        for (int p = 0; p < 4; p++) acc[i][p] = 0ull;
    }

    float4 ra0, ra1, rb0, rb1;

    auto ldg_tile = [&](int kt) {
        int k0 = kt * BK;
        const float* Ap;
        const float* Wp;
        if (k0 < KDIM_) { Ap = x; Wp = Wih; }
        else            { Ap = h; Wp = Whh; k0 -= KDIM_; }
        ra0 = *reinterpret_cast<const float4*>(&Ap[(size_t)(m0 + aRow)      * KDIM_ + k0 + aK]);
        ra1 = *reinterpret_cast<const float4*>(&Ap[(size_t)(m0 + aRow + 64) * KDIM_ + k0 + aK]);
        rb0 = *reinterpret_cast<const float4*>(&Wp[(size_t)(k0 + bRow)     * HID_ + n0 + bCol]);
        rb1 = *reinterpret_cast<const float4*>(&Wp[(size_t)(k0 + bRow + 8) * HID_ + n0 + bCol]);
    };

    auto sts_tile = [&]() {
        As[(aK + 0) * LDA_S + aRow] = ra0.x;
        As[(aK + 1) * LDA_S + aRow] = ra0.y;
        As[(aK + 2) * LDA_S + aRow] = ra0.z;
        As[(aK + 3) * LDA_S + aRow] = ra0.w;
        As[(aK + 0) * LDA_S + aRow + 64] = ra1.x;
        As[(aK + 1) * LDA_S + aRow + 64] = ra1.y;
        As[(aK + 2) * LDA_S + aRow + 64] = ra1.z;
        As[(aK + 3) * LDA_S + aRow + 64] = ra1.w;
        *reinterpret_cast<float4*>(&Bs[bRow       * BN + bCol]) = rb0;
        *reinterpret_cast<float4*>(&Bs[(bRow + 8) * BN + bCol]) = rb1;
    };

    constexpr int NKT = (2 * KDIM_) / BK;   // 256 K-tiles

    ldg_tile(0);
    sts_tile();
    __syncthreads();

    for (int kt = 0; kt < NKT; kt++) {
        if (kt + 1 < NKT) ldg_tile(kt + 1);   // register prefetch of next tile

        #pragma unroll
        for (int k = 0; k < BK; k++) {
            const float4 av0 = *reinterpret_cast<const float4*>(&As[k * LDA_S + ty * 8]);
            const float4 av1 = *reinterpret_cast<const float4*>(&As[k * LDA_S + ty * 8 + 4]);
            const ulonglong2 bv0 = *reinterpret_cast<const ulonglong2*>(&Bs[k * BN + tx * 8]);
            const ulonglong2 bv1 = *reinterpret_cast<const ulonglong2*>(&Bs[k * BN + tx * 8 + 4]);
            const unsigned long long bp0 = bv0.x, bp1 = bv0.y, bp2 = bv1.x, bp3 = bv1.y;
            const float a[8] = {av0.x, av0.y, av0.z, av0.w, av1.x, av1.y, av1.z, av1.w};
            #pragma unroll
            for (int i = 0; i < 8; i++) {
                const unsigned long long ap = pack2_dup(a[i]);
                acc[i][0] = ffma2(ap, bp0, acc[i][0]);
                acc[i][1] = ffma2(ap, bp1, acc[i][1]);
                acc[i][2] = ffma2(ap, bp2, acc[i][2]);
                acc[i][3] = ffma2(ap, bp3, acc[i][3]);
            }
        }

        if (kt + 1 < NKT) {
            __syncthreads();
            sts_tile();
            __syncthreads();
        }
    }

    // Write the 8x8 microtile. Packed f32x2 u64 bit layout == two consecutive floats
    // (little-endian), so store accumulators directly as 16B stores.
    float* out = g_gates + (size_t)gate * BATCH_ * HID_;
    #pragma unroll
    for (int i = 0; i < 8; i++) {
        const size_t row = (size_t)(m0 + ty * 8 + i);
        float* o = &out[row * HID_ + n0 + tx * 8];
        ulonglong2 v0; v0.x = acc[i][0]; v0.y = acc[i][1];
        ulonglong2 v1; v1.x = acc[i][2]; v1.y = acc[i][3];
        *reinterpret_cast<ulonglong2*>(o)     = v0;
        *reinterpret_cast<ulonglong2*>(o + 4) = v1;
    }
}

__device__ __forceinline__ float sigmoid_f(float v) {
    return 1.0f / (1.0f + expf(-v));
}

__device__ __forceinline__ void lstm_one(float gi, float gf, float gc, float go,
                                         float cprev, float& hn, float& cn) {
    const float ig = sigmoid_f(gi);
    const float fg = sigmoid_f(gf);
    const float cg = tanhf(gc);
    const float og = sigmoid_f(go);
    cn = fg * cprev + ig * cg;
    hn = og * tanhf(cn);
}

// out[0 .. B*H)      = h_new
// out[B*H .. 2*B*H)  = c_new
__global__ __launch_bounds__(256) void lstm_epilogue_kernel(
    const float* __restrict__ c,
    const float* __restrict__ b_ih, const float* __restrict__ b_hh,
    float* __restrict__ out)
{
    constexpr size_t BH = (size_t)BATCH_ * HID_;
    const size_t idx = ((size_t)blockIdx.x * blockDim.x + threadIdx.x) * 4;
    if (idx >= BH) return;
    const int n = (int)(idx & (HID_ - 1));

    const float4 g0 = *reinterpret_cast<const float4*>(&g_gates[idx]);
    const float4 g1 = *reinterpret_cast<const float4*>(&g_gates[BH + idx]);
    const float4 g2 = *reinterpret_cast<const float4*>(&g_gates[2 * BH + idx]);
    const float4 g3 = *reinterpret_cast<const float4*>(&g_gates[3 * BH + idx]);

    const float4 bi0 = *reinterpret_cast<const float4*>(&b_ih[0 * HID_ + n]);
    const float4 bi1 = *reinterpret_cast<const float4*>(&b_ih[1 * HID_ + n]);
    const float4 bi2 = *reinterpret_cast<const float4*>(&b_ih[2 * HID_ + n]);
    const float4 bi3 = *reinterpret_cast<const float4*>(&b_ih[3 * HID_ + n]);
    const float4 bh0 = *reinterpret_cast<const float4*>(&b_hh[0 * HID_ + n]);
    const float4 bh1 = *reinterpret_cast<const float4*>(&b_hh[1 * HID_ + n]);
    const float4 bh2 = *reinterpret_cast<const float4*>(&b_hh[2 * HID_ + n]);
    const float4 bh3 = *reinterpret_cast<const float4*>(&b_hh[3 * HID_ + n]);

    const float4 cv = *reinterpret_cast<const float4*>(&c[idx]);

    float4 hn, cn;
    lstm_one(g0.x + bi0.x + bh0.x, g1.x + bi1.x + bh1.x,
             g2.x + bi2.x + bh2.x, g3.x + bi3.x + bh3.x, cv.x, hn.x, cn.x);
    lstm_one(g0.y + bi0.y + bh0.y, g1.y + bi1.y + bh1.y,
             g2.y + bi2.y + bh2.y, g3.y + bi3.y + bh3.y, cv.y, hn.y, cn.y);
    lstm_one(g0.z + bi0.z + bh0.z, g1.z + bi1.z + bh1.z,
             g2.z + bi2.z + bh2.z, g3.z + bi3.z + bh3.z, cv.z, hn.z, cn.z);
    lstm_one(g0.w + bi0.w + bh0.w, g1.w + bi1.w + bh1.w,
             g2.w + bi2.w + bh2.w, g3.w + bi3.w + bh3.w, cv.w, hn.w, cn.w);

    *reinterpret_cast<float4*>(&out[idx])      = hn;
    *reinterpret_cast<float4*>(&out[BH + idx]) = cn;
}

extern "C" void kernel_launch(void* const* d_in, const int* in_sizes, int n_in,
                              void* d_out, int out_size)
{
    (void)in_sizes; (void)n_in; (void)out_size;
    const float* x    = (const float*)d_in[0];
    const float* h    = (const float*)d_in[1];
    const float* c    = (const float*)d_in[2];
    const float* w_ih = (const float*)d_in[3];
    const float* w_hh = (const float*)d_in[4];
    const float* b_ih = (const float*)d_in[5];
    const float* b_hh = (const float*)d_in[6];
    float* out = (float*)d_out;

    // blockIdx.x = batch tile (fastest) so one wave's CTAs share each weight panel in L2
    dim3 grid(BATCH_ / BM, HID_ / BN, 4);
    gates_gemm_kernel<<<grid, 256>>>(x, h, w_ih, w_hh);

    constexpr size_t BH = (size_t)BATCH_ * HID_;
    const int blocks = (int)(BH / 4 / 256);
    lstm_epilogue_kernel<<<blocks, 256>>>(c, b_ih, b_hh, out);
}

// round 10
// speedup vs baseline: 2.3841x; 2.3841x over previous
#include <cuda_runtime.h>
#include <cuda_bf16.h>
#include <cstdint>
#include <math.h>

#define BATCH_ 4096
#define HID_   2048
#define KTOT   4096            // K = INPUT(2048 from x) ++ HIDDEN(2048 from h)
#define NFLAT  8192            // 4 gates * 2048 flattened N
#define BH     ((size_t)BATCH_ * HID_)

// GEMM tiling
#define BM 128
#define BN 256
#define BK 32
#define STAGES 4
#define NKC (KTOT / BK)        // 128 k-iterations

// SMEM stage layout (48KB per stage, 4 stages = 192KB)
#define OFF_AHI 0
#define OFF_ALO 8192
#define OFF_BHI 16384
#define OFF_BLO 32768
#define ST_BYTES 49152
#define SMEM_TOTAL (STAGES * ST_BYTES)

// ---------------- scratch (device globals; allocation-free) ----------------
__device__ __nv_bfloat16 g_A_hi[(size_t)BATCH_ * KTOT];    // [b][k]       32MB
__device__ __nv_bfloat16 g_A_lo[(size_t)BATCH_ * KTOT];
__device__ __nv_bfloat16 g_B_hi[(size_t)NFLAT * KTOT];     // [g*2048+n][k] 64MB
__device__ __nv_bfloat16 g_B_lo[(size_t)NFLAT * KTOT];
__device__ float         g_gates[(size_t)4 * BATCH_ * HID_]; // [g][b][n]  134MB

// ---------------- PTX helpers (base ISA only — no 'a'-feature instructions) --
__device__ __forceinline__ uint32_t smem_u32(const void* p) {
    uint32_t a;
    asm("{ .reg .u64 t; cvta.to.shared.u64 t, %1; cvt.u32.u64 %0, t; }" : "=r"(a) : "l"(p));
    return a;
}
__device__ __forceinline__ void cp16(uint32_t dst, const void* src) {
    asm volatile("cp.async.cg.shared.global [%0], [%1], 16;" :: "r"(dst), "l"(src));
}
__device__ __forceinline__ void cp_commit() { asm volatile("cp.async.commit_group;" ::: "memory"); }
template <int N>
__device__ __forceinline__ void cp_wait() { asm volatile("cp.async.wait_group %0;" :: "n"(N) : "memory"); }

__device__ __forceinline__ void ldsm4(uint32_t* r, uint32_t addr) {
    asm volatile("ldmatrix.sync.aligned.m8n8.x4.shared.b16 {%0,%1,%2,%3}, [%4];"
                 : "=r"(r[0]), "=r"(r[1]), "=r"(r[2]), "=r"(r[3]) : "r"(addr));
}
__device__ __forceinline__ void mma16816(float* d, const uint32_t* a, uint32_t b0, uint32_t b1) {
    asm volatile(
        "mma.sync.aligned.m16n8k16.row.col.f32.bf16.bf16.f32 "
        "{%0,%1,%2,%3}, {%4,%5,%6,%7}, {%8,%9}, {%0,%1,%2,%3};"
        : "+f"(d[0]), "+f"(d[1]), "+f"(d[2]), "+f"(d[3])
        : "r"(a[0]), "r"(a[1]), "r"(a[2]), "r"(a[3]), "r"(b0), "r"(b1));
}

// 64B-row swizzle: 16B-column index XORed with (row>>1)&3 -> conflict-free for
// cp.async 16B stores and ldmatrix 8-row groups.
__device__ __forceinline__ uint32_t sw64(int row, int k2) {
    return (uint32_t)(row * 64 + ((k2 ^ ((row >> 1) & 3)) << 4));
}

// ---------------- conversion kernels ----------------
__device__ __forceinline__ void split_store4(__nv_bfloat16* hi, __nv_bfloat16* lo, float4 v) {
    __nv_bfloat16 h0 = __float2bfloat16(v.x);
    __nv_bfloat16 h1 = __float2bfloat16(v.y);
    __nv_bfloat16 h2 = __float2bfloat16(v.z);
    __nv_bfloat16 h3 = __float2bfloat16(v.w);
    __nv_bfloat16 l0 = __float2bfloat16(v.x - __bfloat162float(h0));
    __nv_bfloat16 l1 = __float2bfloat16(v.y - __bfloat162float(h1));
    __nv_bfloat16 l2 = __float2bfloat16(v.z - __bfloat162float(h2));
    __nv_bfloat16 l3 = __float2bfloat16(v.w - __bfloat162float(h3));
    __nv_bfloat162* hp = reinterpret_cast<__nv_bfloat162*>(hi);
    __nv_bfloat162* lp = reinterpret_cast<__nv_bfloat162*>(lo);
    hp[0] = __halves2bfloat162(h0, h1);
    hp[1] = __halves2bfloat162(h2, h3);
    lp[0] = __halves2bfloat162(l0, l1);
    lp[1] = __halves2bfloat162(l2, l3);
}

__global__ __launch_bounds__(256) void conv_a_kernel(const float* __restrict__ x,
                                                     const float* __restrict__ h) {
    const size_t e = ((size_t)blockIdx.x * 256 + threadIdx.x) * 4;
    if (e >= (size_t)BATCH_ * 2048) return;
    const int row = (int)(e >> 11);
    const int col = (int)(e & 2047);
    const float4 xv = *reinterpret_cast<const float4*>(x + e);
    const float4 hv = *reinterpret_cast<const float4*>(h + e);
    const size_t base = (size_t)row * KTOT + col;
    split_store4(g_A_hi + base, g_A_lo + base, xv);
    split_store4(g_A_hi + base + 2048, g_A_lo + base + 2048, hv);
}

// Transpose w[g][k][n] (k 0..4095: first 2048 from w_ih, rest w_hh) -> Bt[g*2048+n][k], hi/lo
__global__ __launch_bounds__(256) void conv_w_kernel(const float* __restrict__ w_ih,
                                                     const float* __restrict__ w_hh) {
    __shared__ float t[32][33];
    const int g = blockIdx.z;
    const int kt = blockIdx.y * 32;
    const int nt = blockIdx.x * 32;
    const int tx = threadIdx.x;   // 32
    const int ty = threadIdx.y;   // 8
#pragma unroll
    for (int r = 0; r < 4; r++) {
        const int kk = kt + ty + r * 8;
        const float* src = (kk < 2048)
            ? (w_ih + ((size_t)g * 2048 + kk) * HID_)
            : (w_hh + ((size_t)g * 2048 + (kk - 2048)) * HID_);
        t[ty + r * 8][tx] = src[nt + tx];
    }
    __syncthreads();
#pragma unroll
    for (int r = 0; r < 4; r++) {
        const int nn = nt + ty + r * 8;
        const float v = t[tx][ty + r * 8];
        const __nv_bfloat16 hi = __float2bfloat16(v);
        const __nv_bfloat16 lo = __float2bfloat16(v - __bfloat162float(hi));
        const size_t off = ((size_t)g * HID_ + nn) * KTOT + kt + tx;
        g_B_hi[off] = hi;
        g_B_lo[off] = lo;
    }
}

// ---------------- bf16 3-split tensor-core GEMM ----------------
// gates[flatN][b accumulation]: D[m, nf] = sum_k A[m,k] * Bt[nf,k], nf in [0,8192)
// CTA: 128(m) x 256(n); 8 warps in 2x4 grid; warp tile 64x64.
__global__ __launch_bounds__(256, 1) void gates_mma_kernel() {
    extern __shared__ char smem[];
    const uint32_t sb = smem_u32(smem);
    const int tid = threadIdx.x;
    const int wid = tid >> 5;
    const int lid = tid & 31;
    const int wr = wid >> 2;       // 0..1  (64-row band)
    const int wc = wid & 3;        // 0..3  (64-col band)
    const int m0 = blockIdx.x * BM;
    const int n0f = blockIdx.y * BN;

    const __nv_bfloat16* __restrict__ Ahi = g_A_hi + (size_t)m0 * KTOT;
    const __nv_bfloat16* __restrict__ Alo = g_A_lo + (size_t)m0 * KTOT;
    const __nv_bfloat16* __restrict__ Bhi = g_B_hi + (size_t)n0f * KTOT;
    const __nv_bfloat16* __restrict__ Blo = g_B_lo + (size_t)n0f * KTOT;

    float acc[4][8][4];
#pragma unroll
    for (int i = 0; i < 4; i++)
#pragma unroll
        for (int j = 0; j < 8; j++)
#pragma unroll
            for (int p = 0; p < 4; p++) acc[i][j][p] = 0.0f;

    auto load_stage = [&](int kt) {
        const int s = kt & (STAGES - 1);
        const int k0 = kt * BK;
        const uint32_t base = sb + (uint32_t)s * ST_BYTES;
        // A: 128 rows x 32k, hi+lo (512 x 16B each)
#pragma unroll
        for (int j = 0; j < 2; j++) {
            const int idx = tid + j * 256;
            const int row = idx >> 2, k2 = idx & 3;
            const uint32_t off = sw64(row, k2);
            const size_t go = (size_t)row * KTOT + k0 + k2 * 8;
            cp16(base + OFF_AHI + off, Ahi + go);
            cp16(base + OFF_ALO + off, Alo + go);
        }
        // B: 256 rows x 32k, hi+lo (1024 x 16B each)
#pragma unroll
        for (int j = 0; j < 4; j++) {
            const int idx = tid + j * 256;
            const int row = idx >> 2, k2 = idx & 3;
            const uint32_t off = sw64(row, k2);
            const size_t go = (size_t)row * KTOT + k0 + k2 * 8;
            cp16(base + OFF_BHI + off, Bhi + go);
            cp16(base + OFF_BLO + off, Blo + go);
        }
    };

#pragma unroll
    for (int kt = 0; kt < STAGES - 1; kt++) { load_stage(kt); cp_commit(); }

    const int lrow = lid & 15;      // ldmatrix row-within-16
    const int lk2  = lid >> 4;      // ldmatrix 16B-column half

    for (int kt = 0; kt < NKC; kt++) {
        cp_wait<STAGES - 2>();
        __syncthreads();   // stage kt ready; also WAR-guards the refill below

        const uint32_t base = sb + (uint32_t)(kt & (STAGES - 1)) * ST_BYTES;
        const uint32_t aHi = base + OFF_AHI, aLo = base + OFF_ALO;
        const uint32_t bHi = base + OFF_BHI, bLo = base + OFF_BLO;

#pragma unroll
        for (int ko = 0; ko < 2; ko++) {           // two k16 steps per k32 stage
            uint32_t ah[4][4], al[4][4];
#pragma unroll
            for (int i = 0; i < 4; i++) {
                const int row = wr * 64 + i * 16 + lrow;
                const uint32_t off = sw64(row, ko * 2 + lk2);
                ldsm4(ah[i], aHi + off);
                ldsm4(al[i], aLo + off);
            }
#pragma unroll
            for (int nt = 0; nt < 4; nt++) {       // four n16 tiles -> 8 n8 frags
                const int row = wc * 64 + nt * 16 + lrow;
                const uint32_t off = sw64(row, ko * 2 + lk2);
                uint32_t bh[4], bl[4];
                ldsm4(bh, bHi + off);
                ldsm4(bl, bLo + off);
#pragma unroll
                for (int i = 0; i < 4; i++) {
                    mma16816(acc[i][2 * nt],     ah[i], bh[0], bh[2]);
                    mma16816(acc[i][2 * nt + 1], ah[i], bh[1], bh[3]);
                    mma16816(acc[i][2 * nt],     al[i], bh[0], bh[2]);
                    mma16816(acc[i][2 * nt + 1], al[i], bh[1], bh[3]);
                    mma16816(acc[i][2 * nt],     ah[i], bl[0], bl[2]);
                    mma16816(acc[i][2 * nt + 1], ah[i], bl[1], bl[3]);
                }
            }
        }

        const int np = kt + STAGES - 1;
        if (np < NKC) load_stage(np);
        cp_commit();   // commit every iteration (possibly empty) to keep counts aligned
    }

    // Store to g_gates[g][b][n]; CTA's 256 n-cols sit inside one gate (2048 % 256 == 0)
    const int g = n0f >> 11;
    const int nb = (n0f & 2047) + wc * 64 + (lid & 3) * 2;
    float* __restrict__ gp = g_gates + (size_t)g * BH;
#pragma unroll
    for (int i = 0; i < 4; i++) {
        const int r0 = m0 + wr * 64 + i * 16 + (lid >> 2);
#pragma unroll
        for (int n8 = 0; n8 < 8; n8++) {
            const int col = nb + n8 * 8;
            float2 v0; v0.x = acc[i][n8][0]; v0.y = acc[i][n8][1];
            float2 v1; v1.x = acc[i][n8][2]; v1.y = acc[i][n8][3];
            *reinterpret_cast<float2*>(gp + (size_t)r0 * HID_ + col)       = v0;
            *reinterpret_cast<float2*>(gp + (size_t)(r0 + 8) * HID_ + col) = v1;
        }
    }
}

// ---------------- epilogue (proven in R8: ~46us) ----------------
__device__ __forceinline__ float sigmoid_f(float v) { return 1.0f / (1.0f + expf(-v)); }

__device__ __forceinline__ void lstm_one(float gi, float gf, float gc, float go,
                                         float cprev, float& hn, float& cn) {
    const float ig = sigmoid_f(gi);
    const float fg = sigmoid_f(gf);
    const float cg = tanhf(gc);
    const float og = sigmoid_f(go);
    cn = fg * cprev + ig * cg;
    hn = og * tanhf(cn);
}

__global__ __launch_bounds__(256) void lstm_epilogue_kernel(
    const float* __restrict__ c,
    const float* __restrict__ b_ih, const float* __restrict__ b_hh,
    float* __restrict__ out)
{
    const size_t idx = ((size_t)blockIdx.x * blockDim.x + threadIdx.x) * 4;
    if (idx >= BH) return;
    const int n = (int)(idx & (HID_ - 1));

    const float4 g0 = *reinterpret_cast<const float4*>(&g_gates[idx]);
    const float4 g1 = *reinterpret_cast<const float4*>(&g_gates[BH + idx]);
    const float4 g2 = *reinterpret_cast<const float4*>(&g_gates[2 * BH + idx]);
    const float4 g3 = *reinterpret_cast<const float4*>(&g_gates[3 * BH + idx]);

    const float4 bi0 = *reinterpret_cast<const float4*>(&b_ih[0 * HID_ + n]);
    const float4 bi1 = *reinterpret_cast<const float4*>(&b_ih[1 * HID_ + n]);
    const float4 bi2 = *reinterpret_cast<const float4*>(&b_ih[2 * HID_ + n]);
    const float4 bi3 = *reinterpret_cast<const float4*>(&b_ih[3 * HID_ + n]);
    const float4 bh0 = *reinterpret_cast<const float4*>(&b_hh[0 * HID_ + n]);
    const float4 bh1 = *reinterpret_cast<const float4*>(&b_hh[1 * HID_ + n]);
    const float4 bh2 = *reinterpret_cast<const float4*>(&b_hh[2 * HID_ + n]);
    const float4 bh3 = *reinterpret_cast<const float4*>(&b_hh[3 * HID_ + n]);

    const float4 cv = *reinterpret_cast<const float4*>(&c[idx]);

    float4 hn, cn;
    lstm_one(g0.x + bi0.x + bh0.x, g1.x + bi1.x + bh1.x,
             g2.x + bi2.x + bh2.x, g3.x + bi3.x + bh3.x, cv.x, hn.x, cn.x);
    lstm_one(g0.y + bi0.y + bh0.y, g1.y + bi1.y + bh1.y,
             g2.y + bi2.y + bh2.y, g3.y + bi3.y + bh3.y, cv.y, hn.y, cn.y);
    lstm_one(g0.z + bi0.z + bh0.z, g1.z + bi1.z + bh1.z,
             g2.z + bi2.z + bh2.z, g3.z + bi3.z + bh3.z, cv.z, hn.z, cn.z);
    lstm_one(g0.w + bi0.w + bh0.w, g1.w + bi1.w + bh1.w,
             g2.w + bi2.w + bh2.w, g3.w + bi3.w + bh3.w, cv.w, hn.w, cn.w);

    *reinterpret_cast<float4*>(&out[idx])      = hn;
    *reinterpret_cast<float4*>(&out[BH + idx]) = cn;
}

// ---------------- launch ----------------
extern "C" void kernel_launch(void* const* d_in, const int* in_sizes, int n_in,
                              void* d_out, int out_size)
{
    (void)in_sizes; (void)n_in; (void)out_size;
    const float* x    = (const float*)d_in[0];
    const float* h    = (const float*)d_in[1];
    const float* c    = (const float*)d_in[2];
    const float* w_ih = (const float*)d_in[3];
    const float* w_hh = (const float*)d_in[4];
    const float* b_ih = (const float*)d_in[5];
    const float* b_hh = (const float*)d_in[6];
    float* out = (float*)d_out;

    // 1) split x|h into bf16 hi/lo A [4096, 4096]
    conv_a_kernel<<<(BATCH_ * 2048 / 4 + 255) / 256, 256>>>(x, h);

    // 2) transpose + split weights -> Bt [8192, 4096] hi/lo
    dim3 gw(HID_ / 32, KTOT / 32, 4);
    conv_w_kernel<<<gw, dim3(32, 8)>>>(w_ih, w_hh);

    // 3) tensor-core GEMM (m-fastest grid for B-panel L2 reuse)
    static int smem_set = 0;
    if (!smem_set) {
        cudaFuncSetAttribute(gates_mma_kernel,
                             cudaFuncAttributeMaxDynamicSharedMemorySize, SMEM_TOTAL);
        smem_set = 1;
    }
    dim3 gg(BATCH_ / BM, NFLAT / BN);   // (32, 32)
    gates_mma_kernel<<<gg, 256, SMEM_TOTAL>>>();

    // 4) fused LSTM pointwise epilogue
    lstm_epilogue_kernel<<<(int)(BH / 4 / 256), 256>>>(c, b_ih, b_hh, out);
}